// round 1
// baseline (speedup 1.0000x reference)
#include <cuda_runtime.h>

#define NN 100000
#define HH 128
#define EE 1600000
#define OUTD 64
#define ALPHA_C 0.6f
#define BETA_C 0.1f   // (1-ALPHA)/L

// ---------------- scratch (device globals: allocation-free) ----------------
__device__ float g_Z[(size_t)NN * HH];      // current layer activations
__device__ float g_y[(size_t)NN * HH];      // y = (Z@W)*dis[row]
__device__ float g_zinit[(size_t)NN * HH];
__device__ float g_zsum[(size_t)NN * HH];
__device__ float g_dis[NN];
__device__ int   g_deg[NN];
__device__ int   g_cnt[NN];
__device__ int   g_rowptr[NN];
__device__ int   g_col[EE];
__device__ int   g_bsum[128];
__device__ int   g_is64;

// ---------------- edge dtype detection ----------------
__global__ void k_detect(const void* ei) {
    if (threadIdx.x == 0) {
        const long long* p = (const long long*)ei;
        int is64 = 1;
        for (int i = 0; i < 64; i++) {
            long long v = p[i];
            if (v < 0 || v >= NN) { is64 = 0; break; }
        }
        g_is64 = is64;
    }
}

__device__ __forceinline__ int edge_at(const void* ei, long long i) {
    return g_is64 ? (int)((const long long*)ei)[i] : ((const int*)ei)[i];
}

// ---------------- CSR build ----------------
__global__ void k_zero() {
    int i = blockIdx.x * blockDim.x + threadIdx.x;
    if (i < NN) { g_deg[i] = 0; g_cnt[i] = 0; }
}

__global__ void k_hist(const void* ei) {
    int e = blockIdx.x * blockDim.x + threadIdx.x;
    if (e < EE) atomicAdd(&g_deg[edge_at(ei, (long long)EE + e)], 1);
}

__global__ void k_dis() {
    int i = blockIdx.x * blockDim.x + threadIdx.x;
    if (i < NN) g_dis[i] = rsqrtf((float)g_deg[i] + 1.0f);
}

// block scans 1024 elements (256 thr x 4); writes exclusive-within-block
__global__ void k_scan1() {
    __shared__ int sm[256];
    int b = blockIdx.x, t = threadIdx.x;
    int base = b * 1024 + t * 4;
    int v[4];
#pragma unroll
    for (int j = 0; j < 4; j++) {
        int i = base + j;
        v[j] = (i < NN) ? g_deg[i] : 0;
    }
    int s = v[0] + v[1] + v[2] + v[3];
    sm[t] = s;
    __syncthreads();
    for (int off = 1; off < 256; off <<= 1) {
        int x = sm[t];
        if (t >= off) x += sm[t - off];
        __syncthreads();
        sm[t] = x;
        __syncthreads();
    }
    int ex = sm[t] - s;  // exclusive prefix of this thread's chunk
    int run = 0;
#pragma unroll
    for (int j = 0; j < 4; j++) {
        int i = base + j;
        if (i < NN) g_rowptr[i] = ex + run;
        run += v[j];
    }
    if (t == 255) g_bsum[b] = sm[255];
}

__global__ void k_scan2(int nb) {  // single block, 128 threads
    __shared__ int sm[128];
    int t = threadIdx.x;
    int v = (t < nb) ? g_bsum[t] : 0;
    sm[t] = v;
    __syncthreads();
    for (int off = 1; off < 128; off <<= 1) {
        int x = sm[t];
        if (t >= off) x += sm[t - off];
        __syncthreads();
        sm[t] = x;
        __syncthreads();
    }
    g_bsum[t] = sm[t] - v;  // exclusive
}

__global__ void k_scan3() {
    int i = blockIdx.x * blockDim.x + threadIdx.x;
    if (i < NN) g_rowptr[i] += g_bsum[i >> 10];
}

__global__ void k_fill(const void* ei) {
    int e = blockIdx.x * blockDim.x + threadIdx.x;
    if (e >= EE) return;
    int s = edge_at(ei, e);
    int d = edge_at(ei, (long long)EE + e);
    int pos = g_rowptr[d] + atomicAdd(&g_cnt[d], 1);
    g_col[pos] = s;
}

// ---------------- GEMM: M x 128 @ 128 x BN ----------------
// MODE 0: C = A@B + bias ; write g_Z, g_zinit, g_zsum=0        (A = x)
// MODE 1: g_y = (g_Z @ B) * dis[row]                           (A unused)
// MODE 2: C = (ALPHA*g_zinit + BETA*g_zsum) @ B + bias -> out  (A unused)
template <int BN, int TN, int MODE>
__global__ void k_gemm(const float* __restrict__ A, const float* __restrict__ B,
                       const float* __restrict__ bias, float* __restrict__ C) {
    constexpr int BM = 64, BK = 16, TM = 8;
    __shared__ float As[BK][BM];
    __shared__ float Bs[BK][BN];

    int row0 = blockIdx.x * BM;
    int tid = threadIdx.x;
    int trow = tid >> 5;   // 0..7
    int tcol = tid & 31;   // 0..31

    float acc[TM][TN];
#pragma unroll
    for (int r = 0; r < TM; r++)
#pragma unroll
        for (int c = 0; c < TN; c++) acc[r][c] = 0.0f;

    int ar = tid >> 2;          // 0..63 (A tile row)
    int ac = (tid & 3) * 4;     // 0,4,8,12 (A tile col base)

#pragma unroll
    for (int kk = 0; kk < 8; kk++) {
        int k0 = kk * 16;
        // --- load A tile (64 x 16), store transposed ---
        float4 a4 = make_float4(0.f, 0.f, 0.f, 0.f);
        int grow = row0 + ar;
        if (grow < NN) {
            size_t off = (size_t)grow * 128 + k0 + ac;
            if (MODE == 0) {
                a4 = *(const float4*)(A + off);
            } else if (MODE == 1) {
                a4 = *(const float4*)(g_Z + off);
            } else {
                float4 zi = *(const float4*)(g_zinit + off);
                float4 zs = *(const float4*)(g_zsum + off);
                a4.x = ALPHA_C * zi.x + BETA_C * zs.x;
                a4.y = ALPHA_C * zi.y + BETA_C * zs.y;
                a4.z = ALPHA_C * zi.z + BETA_C * zs.z;
                a4.w = ALPHA_C * zi.w + BETA_C * zs.w;
            }
        }
        As[ac + 0][ar] = a4.x;
        As[ac + 1][ar] = a4.y;
        As[ac + 2][ar] = a4.z;
        As[ac + 3][ar] = a4.w;
        // --- load B tile (16 x BN) ---
        if (BN == 128) {
#pragma unroll
            for (int q = 0; q < 2; q++) {
                int i = tid * 2 + q;
                int br = i >> 5, bc = i & 31;
                float4 b4 = *(const float4*)(B + (size_t)(k0 + br) * BN + bc * 4);
                ((float4*)&Bs[br][0])[bc] = b4;
            }
        } else {  // BN == 64
            int br = tid >> 4, bc = tid & 15;
            float4 b4 = *(const float4*)(B + (size_t)(k0 + br) * BN + bc * 4);
            ((float4*)&Bs[br][0])[bc] = b4;
        }
        __syncthreads();
#pragma unroll
        for (int k = 0; k < 16; k++) {
            float ra[TM];
            const float4* av = (const float4*)&As[k][trow * 8];
            float4 ra0 = av[0], ra1 = av[1];
            ra[0] = ra0.x; ra[1] = ra0.y; ra[2] = ra0.z; ra[3] = ra0.w;
            ra[4] = ra1.x; ra[5] = ra1.y; ra[6] = ra1.z; ra[7] = ra1.w;
            float rb[TN];
            if (TN == 4) {
                float4 b4 = *(const float4*)&Bs[k][tcol * 4];
                rb[0] = b4.x; rb[1] = b4.y; rb[2] = b4.z; rb[3] = b4.w;
            } else {
                float2 b2 = *(const float2*)&Bs[k][tcol * 2];
                rb[0] = b2.x; rb[1] = b2.y;
            }
#pragma unroll
            for (int r = 0; r < TM; r++)
#pragma unroll
                for (int c = 0; c < TN; c++) acc[r][c] = fmaf(ra[r], rb[c], acc[r][c]);
        }
        __syncthreads();
    }

    // --- epilogue ---
#pragma unroll
    for (int r = 0; r < TM; r++) {
        int grow = row0 + trow * 8 + r;
        if (grow >= NN) continue;
        if (MODE == 0) {
            int n = tcol * 4;
            float4 bv = *(const float4*)(bias + n);
            float4 v;
            v.x = acc[r][0] + bv.x; v.y = acc[r][1] + bv.y;
            v.z = acc[r][2] + bv.z; v.w = acc[r][3] + bv.w;
            size_t off = (size_t)grow * 128 + n;
            *(float4*)(g_Z + off) = v;
            *(float4*)(g_zinit + off) = v;
            *(float4*)(g_zsum + off) = make_float4(0.f, 0.f, 0.f, 0.f);
        } else if (MODE == 1) {
            float d = g_dis[grow];
            int n = tcol * 4;
            float4 v;
            v.x = acc[r][0] * d; v.y = acc[r][1] * d;
            v.z = acc[r][2] * d; v.w = acc[r][3] * d;
            *(float4*)(g_y + (size_t)grow * 128 + n) = v;
        } else {
            int n = tcol * 2;
            float2 v;
            v.x = acc[r][0] + bias[n];
            v.y = acc[r][1] + bias[n + 1];
            *(float2*)(C + (size_t)grow * OUTD + n) = v;
        }
    }
}

// ---------------- aggregation: one warp per dst node ----------------
// Z[d] = relu( dis[d]*( sum_{s in nbr(d)} y[s] + y[d] ) + b ); zsum[d] += Z[d]
__global__ void k_agg(const float* __restrict__ bias) {
    int warp = (blockIdx.x * blockDim.x + threadIdx.x) >> 5;
    int lane = threadIdx.x & 31;
    if (warp >= NN) return;
    int d = warp;
    int start = g_rowptr[d];
    int len = g_deg[d];
    const float4* y4 = (const float4*)g_y;
    float4 acc = y4[(size_t)d * 32 + lane];  // self term y[d]
    int end = start + len;
    for (int j0 = start; j0 < end; j0 += 32) {
        int c = (j0 + lane < end) ? g_col[j0 + lane] : 0;
        int m = end - j0; if (m > 32) m = 32;
        for (int t = 0; t < m; t++) {
            int s = __shfl_sync(0xffffffffu, c, t);
            float4 v = y4[(size_t)s * 32 + lane];
            acc.x += v.x; acc.y += v.y; acc.z += v.z; acc.w += v.w;
        }
    }
    float dd = g_dis[d];
    float4 b4 = ((const float4*)bias)[lane];
    float4 o;
    o.x = fmaxf(fmaf(dd, acc.x, b4.x), 0.f);
    o.y = fmaxf(fmaf(dd, acc.y, b4.y), 0.f);
    o.z = fmaxf(fmaf(dd, acc.z, b4.z), 0.f);
    o.w = fmaxf(fmaf(dd, acc.w, b4.w), 0.f);
    ((float4*)g_Z)[(size_t)d * 32 + lane] = o;
    float4* zs4 = (float4*)g_zsum;
    float4 zs = zs4[(size_t)d * 32 + lane];
    zs.x += o.x; zs.y += o.y; zs.z += o.z; zs.w += o.w;
    zs4[(size_t)d * 32 + lane] = zs;
}

// ---------------- launch ----------------
extern "C" void kernel_launch(void* const* d_in, const int* in_sizes, int n_in,
                              void* d_out, int out_size) {
    const float* x     = (const float*)d_in[0];
    const void*  ei    = d_in[1];
    const float* W1    = (const float*)d_in[2];
    const float* b1    = (const float*)d_in[3];
    const float* convW = (const float*)d_in[4];
    const float* convB = (const float*)d_in[5];
    const float* W2    = (const float*)d_in[6];
    const float* b2    = (const float*)d_in[7];
    float* out = (float*)d_out;

    const int NB_N = (NN + 255) / 256;        // 391
    const int NB_E = (EE + 255) / 256;        // 6250
    const int NB_SCAN = (NN + 1023) / 1024;   // 98
    const int NB_GEMM = (NN + 63) / 64;       // 1563
    const int NB_AGG = (NN * 32 + 255) / 256; // 12500

    k_detect<<<1, 32>>>(ei);
    k_zero<<<NB_N, 256>>>();
    k_hist<<<NB_E, 256>>>(ei);
    k_dis<<<NB_N, 256>>>();
    k_scan1<<<NB_SCAN, 256>>>();
    k_scan2<<<1, 128>>>(NB_SCAN);
    k_scan3<<<NB_N, 256>>>();
    k_fill<<<NB_E, 256>>>(ei);

    // layer 0 input: Z = x@W1 + b1 ; zinit = Z ; zsum = 0
    k_gemm<128, 4, 0><<<NB_GEMM, 256>>>(x, W1, b1, nullptr);

    for (int l = 0; l < 4; l++) {
        k_gemm<128, 4, 1><<<NB_GEMM, 256>>>(nullptr, convW + (size_t)l * HH * HH,
                                            nullptr, nullptr);
        k_agg<<<NB_AGG, 256>>>(convB + (size_t)l * HH);
    }

    // out = (ALPHA*zinit + BETA*zsum) @ W2 + b2
    k_gemm<64, 2, 2><<<NB_GEMM, 256>>>(nullptr, W2, b2, out);
}

// round 5
// speedup vs baseline: 1.0098x; 1.0098x over previous
#include <cuda_runtime.h>
#include <cstdint>

#define NN 100000
#define HH 128
#define EE 1600000
#define OUTD 64
#define ALPHA_C 0.6f
#define BETA_C 0.1f   // (1-ALPHA)/L

// ---------------- scratch (device globals: allocation-free) ----------------
__device__ float g_Z[(size_t)NN * HH];      // current layer activations
__device__ float g_y[(size_t)NN * HH];      // y = (Z@W)*dis[row]
__device__ float g_zinit[(size_t)NN * HH];
__device__ float g_zsum[(size_t)NN * HH];
__device__ float g_dis[NN];
__device__ int   g_deg[NN];
__device__ int   g_cnt[NN];
__device__ int   g_rowptr[NN];
__device__ int   g_col[EE];
__device__ int   g_bsum[128];
__device__ int   g_is64;

// ---------------- f32x2 helpers ----------------
__device__ __forceinline__ unsigned long long bcast2(float v) {
    unsigned long long r;
    asm("mov.b64 %0, {%1, %1};" : "=l"(r) : "f"(v));
    return r;
}
__device__ __forceinline__ void fma2(unsigned long long& acc, unsigned long long a,
                                     unsigned long long b) {
    asm("fma.rn.f32x2 %0, %1, %2, %0;" : "+l"(acc) : "l"(a), "l"(b));
}
__device__ __forceinline__ float2 unpk(unsigned long long v) {
    float2 r;
    asm("mov.b64 {%0, %1}, %2;" : "=f"(r.x), "=f"(r.y) : "l"(v));
    return r;
}

// ---------------- edge dtype detection ----------------
__global__ void k_detect(const void* ei) {
    if (threadIdx.x == 0) {
        const long long* p = (const long long*)ei;
        int is64 = 1;
        for (int i = 0; i < 64; i++) {
            long long v = p[i];
            if (v < 0 || v >= NN) { is64 = 0; break; }
        }
        g_is64 = is64;
    }
}

__device__ __forceinline__ int edge_at(const void* ei, long long i) {
    return g_is64 ? (int)((const long long*)ei)[i] : ((const int*)ei)[i];
}

// ---------------- CSR build ----------------
__global__ void k_zero() {
    int i = blockIdx.x * blockDim.x + threadIdx.x;
    if (i < NN) { g_deg[i] = 0; g_cnt[i] = 0; }
}

__global__ void k_hist(const void* ei) {
    int e = blockIdx.x * blockDim.x + threadIdx.x;
    if (e < EE) atomicAdd(&g_deg[edge_at(ei, (long long)EE + e)], 1);
}

__global__ void k_dis() {
    int i = blockIdx.x * blockDim.x + threadIdx.x;
    if (i < NN) g_dis[i] = rsqrtf((float)g_deg[i] + 1.0f);
}

__global__ void k_scan1() {
    __shared__ int sm[256];
    int b = blockIdx.x, t = threadIdx.x;
    int base = b * 1024 + t * 4;
    int v[4];
#pragma unroll
    for (int j = 0; j < 4; j++) {
        int i = base + j;
        v[j] = (i < NN) ? g_deg[i] : 0;
    }
    int s = v[0] + v[1] + v[2] + v[3];
    sm[t] = s;
    __syncthreads();
    for (int off = 1; off < 256; off <<= 1) {
        int x = sm[t];
        if (t >= off) x += sm[t - off];
        __syncthreads();
        sm[t] = x;
        __syncthreads();
    }
    int ex = sm[t] - s;
    int run = 0;
#pragma unroll
    for (int j = 0; j < 4; j++) {
        int i = base + j;
        if (i < NN) g_rowptr[i] = ex + run;
        run += v[j];
    }
    if (t == 255) g_bsum[b] = sm[255];
}

__global__ void k_scan2(int nb) {
    __shared__ int sm[128];
    int t = threadIdx.x;
    int v = (t < nb) ? g_bsum[t] : 0;
    sm[t] = v;
    __syncthreads();
    for (int off = 1; off < 128; off <<= 1) {
        int x = sm[t];
        if (t >= off) x += sm[t - off];
        __syncthreads();
        sm[t] = x;
        __syncthreads();
    }
    g_bsum[t] = sm[t] - v;
}

__global__ void k_scan3() {
    int i = blockIdx.x * blockDim.x + threadIdx.x;
    if (i < NN) g_rowptr[i] += g_bsum[i >> 10];
}

__global__ void k_fill(const void* ei) {
    int e = blockIdx.x * blockDim.x + threadIdx.x;
    if (e >= EE) return;
    int s = edge_at(ei, e);
    int d = edge_at(ei, (long long)EE + e);
    int pos = g_rowptr[d] + atomicAdd(&g_cnt[d], 1);
    g_col[pos] = s;
}

// ---------------- GEMM: M x 128 @ 128 x BN (packed f32x2 FMA) ----------------
// MODE 0: C = A@B + bias ; write g_Z, g_zinit, g_zsum=0        (A = x)
// MODE 1: g_y = (g_Z @ B) * dis[row]                           (A unused)
// MODE 2: C = (ALPHA*g_zinit + BETA*g_zsum) @ B + bias -> out  (A unused)
template <int BN, int TN, int MODE>
__global__ void __launch_bounds__(256) k_gemm(const float* __restrict__ A,
                                              const float* __restrict__ B,
                                              const float* __restrict__ bias,
                                              float* __restrict__ C) {
    constexpr int BM = 64, BK = 16;
    __shared__ float As[BK][BM];
    __shared__ float Bs[BK][BN];

    int row0 = blockIdx.x * BM;
    int tid = threadIdx.x;
    int trow = tid >> 5;   // warp id -> 8-row group
    int tcol = tid & 31;   // lane -> column group

    // accumulators: 4 row-pairs x TN cols; b64 = 2 packed f32 (rows 2r2, 2r2+1)
    unsigned long long acc2[4][TN];
#pragma unroll
    for (int r = 0; r < 4; r++)
#pragma unroll
        for (int c = 0; c < TN; c++) acc2[r][c] = 0ULL;

    int ar = tid >> 2;          // 0..63 (A tile row)
    int ac = (tid & 3) * 4;     // 0,4,8,12 (A tile col base)

#pragma unroll
    for (int kk = 0; kk < 8; kk++) {
        int k0 = kk * 16;
        // --- load A tile (64 x 16), store transposed ---
        float4 a4 = make_float4(0.f, 0.f, 0.f, 0.f);
        int grow = row0 + ar;
        if (grow < NN) {
            size_t off = (size_t)grow * 128 + k0 + ac;
            if (MODE == 0) {
                a4 = *(const float4*)(A + off);
            } else if (MODE == 1) {
                a4 = *(const float4*)(g_Z + off);
            } else {
                float4 zi = *(const float4*)(g_zinit + off);
                float4 zs = *(const float4*)(g_zsum + off);
                a4.x = ALPHA_C * zi.x + BETA_C * zs.x;
                a4.y = ALPHA_C * zi.y + BETA_C * zs.y;
                a4.z = ALPHA_C * zi.z + BETA_C * zs.z;
                a4.w = ALPHA_C * zi.w + BETA_C * zs.w;
            }
        }
        As[ac + 0][ar] = a4.x;
        As[ac + 1][ar] = a4.y;
        As[ac + 2][ar] = a4.z;
        As[ac + 3][ar] = a4.w;
        // --- load B tile (16 x BN) ---
        if (BN == 128) {
#pragma unroll
            for (int q = 0; q < 2; q++) {
                int i = tid * 2 + q;
                int br = i >> 5, bc = i & 31;
                float4 b4 = *(const float4*)(B + (size_t)(k0 + br) * BN + bc * 4);
                ((float4*)&Bs[br][0])[bc] = b4;
            }
        } else {  // BN == 64
            int br = tid >> 4, bc = tid & 15;
            float4 b4 = *(const float4*)(B + (size_t)(k0 + br) * BN + bc * 4);
            ((float4*)&Bs[br][0])[bc] = b4;
        }
        __syncthreads();
#pragma unroll
        for (int k = 0; k < 16; k++) {
            // A fragment: 8 consecutive rows -> 4 packed b64 pairs (direct LDS)
            ulonglong2 a01 = *(const ulonglong2*)&As[k][trow * 8];
            ulonglong2 a23 = *(const ulonglong2*)&As[k][trow * 8 + 4];
            unsigned long long ap[4];
            ap[0] = a01.x; ap[1] = a01.y; ap[2] = a23.x; ap[3] = a23.y;
            unsigned long long bb[TN];
            if (TN == 4) {
                float4 b4 = *(const float4*)&Bs[k][tcol * 4];
                bb[0] = bcast2(b4.x); bb[1] = bcast2(b4.y);
                bb[2] = bcast2(b4.z); bb[3] = bcast2(b4.w);
            } else {
                float2 b2 = *(const float2*)&Bs[k][tcol * 2];
                bb[0] = bcast2(b2.x); bb[1] = bcast2(b2.y);
            }
#pragma unroll
            for (int r = 0; r < 4; r++)
#pragma unroll
                for (int c = 0; c < TN; c++) fma2(acc2[r][c], ap[r], bb[c]);
        }
        __syncthreads();
    }

    // --- epilogue ---
#pragma unroll
    for (int r2 = 0; r2 < 4; r2++) {
        float2 u[TN];
#pragma unroll
        for (int c = 0; c < TN; c++) u[c] = unpk(acc2[r2][c]);
#pragma unroll
        for (int h = 0; h < 2; h++) {
            int grow = row0 + trow * 8 + r2 * 2 + h;
            if (grow >= NN) continue;
            if (MODE == 0) {
                int n = tcol * 4;
                float4 bv = *(const float4*)(bias + n);
                float4 v;
                v.x = (h ? u[0].y : u[0].x) + bv.x;
                v.y = (h ? u[1].y : u[1].x) + bv.y;
                v.z = (h ? u[2].y : u[2].x) + bv.z;
                v.w = (h ? u[3].y : u[3].x) + bv.w;
                size_t off = (size_t)grow * 128 + n;
                *(float4*)(g_Z + off) = v;
                *(float4*)(g_zinit + off) = v;
                *(float4*)(g_zsum + off) = make_float4(0.f, 0.f, 0.f, 0.f);
            } else if (MODE == 1) {
                float d = g_dis[grow];
                int n = tcol * 4;
                float4 v;
                v.x = (h ? u[0].y : u[0].x) * d;
                v.y = (h ? u[1].y : u[1].x) * d;
                v.z = (h ? u[2].y : u[2].x) * d;
                v.w = (h ? u[3].y : u[3].x) * d;
                *(float4*)(g_y + (size_t)grow * 128 + n) = v;
            } else {
                int n = tcol * 2;
                float2 v;
                v.x = (h ? u[0].y : u[0].x) + bias[n];
                v.y = (h ? u[1].y : u[1].x) + bias[n + 1];
                *(float2*)(C + (size_t)grow * OUTD + n) = v;
            }
        }
    }
}

// ---------------- aggregation: one warp per dst node ----------------
// Z[d] = relu( dis[d]*( sum_{s in nbr(d)} y[s] + y[d] ) + b ); zsum[d] += Z[d]
__global__ void k_agg(const float* __restrict__ bias) {
    int warp = (blockIdx.x * blockDim.x + threadIdx.x) >> 5;
    int lane = threadIdx.x & 31;
    if (warp >= NN) return;
    int d = warp;
    int start = g_rowptr[d];
    int len = g_deg[d];
    const float4* y4 = (const float4*)g_y;
    float4 acc = y4[(size_t)d * 32 + lane];  // self term y[d]
    int end = start + len;
    for (int j0 = start; j0 < end; j0 += 32) {
        int c = (j0 + lane < end) ? g_col[j0 + lane] : 0;
        int m = end - j0; if (m > 32) m = 32;
        for (int t = 0; t < m; t++) {
            int s = __shfl_sync(0xffffffffu, c, t);
            float4 v = y4[(size_t)s * 32 + lane];
            acc.x += v.x; acc.y += v.y; acc.z += v.z; acc.w += v.w;
        }
    }
    float dd = g_dis[d];
    float4 b4 = ((const float4*)bias)[lane];
    float4 o;
    o.x = fmaxf(fmaf(dd, acc.x, b4.x), 0.f);
    o.y = fmaxf(fmaf(dd, acc.y, b4.y), 0.f);
    o.z = fmaxf(fmaf(dd, acc.z, b4.z), 0.f);
    o.w = fmaxf(fmaf(dd, acc.w, b4.w), 0.f);
    ((float4*)g_Z)[(size_t)d * 32 + lane] = o;
    float4* zs4 = (float4*)g_zsum;
    float4 zs = zs4[(size_t)d * 32 + lane];
    zs.x += o.x; zs.y += o.y; zs.z += o.z; zs.w += o.w;
    zs4[(size_t)d * 32 + lane] = zs;
}

// ---------------- launch ----------------
extern "C" void kernel_launch(void* const* d_in, const int* in_sizes, int n_in,
                              void* d_out, int out_size) {
    const float* x     = (const float*)d_in[0];
    const void*  ei    = d_in[1];
    const float* W1    = (const float*)d_in[2];
    const float* b1    = (const float*)d_in[3];
    const float* convW = (const float*)d_in[4];
    const float* convB = (const float*)d_in[5];
    const float* W2    = (const float*)d_in[6];
    const float* b2    = (const float*)d_in[7];
    float* out = (float*)d_out;

    const int NB_N = (NN + 255) / 256;
    const int NB_E = (EE + 255) / 256;
    const int NB_SCAN = (NN + 1023) / 1024;
    const int NB_GEMM = (NN + 63) / 64;
    const int NB_AGG = (NN * 32 + 255) / 256;

    k_detect<<<1, 32>>>(ei);
    k_zero<<<NB_N, 256>>>();
    k_hist<<<NB_E, 256>>>(ei);
    k_dis<<<NB_N, 256>>>();
    k_scan1<<<NB_SCAN, 256>>>();
    k_scan2<<<1, 128>>>(NB_SCAN);
    k_scan3<<<NB_N, 256>>>();
    k_fill<<<NB_E, 256>>>(ei);

    k_gemm<128, 4, 0><<<NB_GEMM, 256>>>(x, W1, b1, nullptr);

    for (int l = 0; l < 4; l++) {
        k_gemm<128, 4, 1><<<NB_GEMM, 256>>>(nullptr, convW + (size_t)l * HH * HH,
                                            nullptr, nullptr);
        k_agg<<<NB_AGG, 256>>>(convB + (size_t)l * HH);
    }

    k_gemm<64, 2, 2><<<NB_GEMM, 256>>>(nullptr, W2, b2, out);
}